// round 17
// baseline (speedup 1.0000x reference)
#include <cuda_runtime.h>
#include <cuda_fp16.h>
#include <math.h>
#include <stdint.h>

#define SEQT 1024
#define NB   256
#define NIN  256
#define NH   512
#define NSW  128
#define NSD  64
#define NG   2048
#define KZ   768
#define NROWS 2240
#define NTOT 2179
#define NBLK 138             // 128 gates CTAs + 10 dv/ctrl CTAs
#define NKC  48
#define NTHR 512
#define GSTRIDE (NBLK * NTHR)

// gate W slice per u0 (64 rows x 768 fp16): [kc48][q4][lane32][8] = 49152 halfs = 96 KB
#define WG_H  49152
// dv/ctrl W slice (32 rows x 768): [kc48][nh2][lane32][8] = 24576 halfs = 48 KB
#define WD_H  24576
// Z fragment: [kc48][mtile16][lane32][8 halfs]
#define ZTOT_H 196608
// stack GEMM W_s slice per u0: [kc8][ntp4][lane32][8] = 8192 halfs
#define WS_H 8192

// dynamic smem layout (bytes)
#define SMW     0                  // 98304: resident W slice (gate: 96KB / dv: 48KB)
#define SMWS    98304              // 16384
#define SMSF    114688             // 16384: stack_top fp16 A fragments
#define SMGT    131072             // 16384: gates f32 [64][64] (G1 lives here)
#define SMCF    147456             // 3072
#define SMCFO   150528             // 3072
#define SMTOTAL 153600

// ---- device scratch ----
__device__ __half g_WGfrag[32 * WG_H];
__device__ __half g_WDfrag[5 * WD_H];
__device__ __half g_WSfrag[32 * WS_H];
__device__ __half g_Zfrag[ZTOT_H];
__device__ float g_bz[NROWS];
__device__ float g_dv[2][NB * NSW];
__device__ float g_ctrl[NB * 3];
__device__ float g_cf[2][3 * NB];
__device__ float g_c[NB * NH];
__device__ float g_stk[2][NB * NSD * NSW];
__device__ unsigned g_flags[NBLK * 32];

// ---- helpers ----
__device__ __forceinline__ float sigf(float x) { return 1.f / (1.f + expf(-x)); }
__device__ __forceinline__ void store_zfrag(int b, int kk, float v) {
    int kc = kk >> 4, ko = kk & 15;
    int t   = ((b & 7) << 2) | ((ko & 7) >> 1);
    int reg = ((b >> 3) & 1) | (((ko >> 3) & 1) << 1);
    int idx = ((kc * 16 + (b >> 4)) * 32 + t) * 8 + reg * 2 + (ko & 1);
    g_Zfrag[idx] = __float2half(v);
}
__device__ __forceinline__ void store_zfrag2(int b, int kk, float v0, float v1) {
    int kc = kk >> 4, ko = kk & 15;
    int t   = ((b & 7) << 2) | ((ko & 7) >> 1);
    int reg = ((b >> 3) & 1) | (((ko >> 3) & 1) << 1);
    int idx = ((kc * 16 + (b >> 4)) * 32 + t) * 8 + reg * 2;
    *(__half2*)&g_Zfrag[idx] = __floats2half2_rn(v0, v1);
}
__device__ __forceinline__ void store_sfrag2(__half* base, int bl, int k, float v0, float v1) {
    int kc = k >> 4, ko = k & 15;
    int mt = bl >> 4, bm = bl & 15;
    int t   = ((bm & 7) << 2) | ((ko & 7) >> 1);
    int reg = ((bm >> 3) & 1) | (((ko >> 3) & 1) << 1);
    int idx = ((kc * 4 + mt) * 32 + t) * 8 + reg * 2;
    *(__half2*)&base[idx] = __floats2half2_rn(v0, v1);
}

#define MMA_F16(acc, A, b0, b1) asm volatile( \
    "mma.sync.aligned.m16n8k16.row.col.f32.f16.f16.f32 " \
    "{%0,%1,%2,%3},{%4,%5,%6,%7},{%8,%9},{%0,%1,%2,%3};" \
    : "+f"(acc[0]), "+f"(acc[1]), "+f"(acc[2]), "+f"(acc[3]) \
    : "r"(A.x), "r"(A.y), "r"(A.z), "r"(A.w), "r"(b0), "r"(b1))

#define BAR1() asm volatile("bar.sync 1, 256;" ::: "memory")
#define BAR2() asm volatile("bar.sync 2, 256;" ::: "memory")
#define BAR3() asm volatile("bar.sync 3, 256;" ::: "memory")

__device__ __forceinline__ void grid_bar(int epoch) {
    const unsigned tgt = (unsigned)(epoch + 1);
    __syncthreads();
    if (threadIdx.x == 0) {
        asm volatile("st.release.gpu.u32 [%0], %1;"
                     :: "l"(&g_flags[blockIdx.x * 32]), "r"(tgt) : "memory");
    }
    if (threadIdx.x < NBLK) {
        unsigned v;
        do {
            asm volatile("ld.acquire.gpu.u32 %0, [%1];"
                         : "=r"(v) : "l"(&g_flags[threadIdx.x * 32]) : "memory");
        } while (v < tgt);
    }
    __syncthreads();
}

__device__ __forceinline__ float wval(int n, int k,
        const float* Whh, const float* Wih, const float* Dw, const float* Aw) {
    if (n < NG)        return (k < NH) ? Whh[n*NH + k] : Wih[n*(NIN+NSW) + (k-NH)];
    if (n < NG + NSW)  return (k < NH) ? Dw[(n-NG)*NH + k] : 0.f;
    if (n < NTOT)      return (k < NH) ? Aw[(n-NG-NSW)*NH + k] : 0.f;
    return 0.f;
}

// blend(tb) over run range [lo_, hi_): executed by upper 256 threads (ut 0..255).
__device__ __forceinline__ void run_blend(int tb, int ut, int lo_, int hi_, const float* cfo) {
    const float* __restrict__ sold = g_stk[tb & 1];
    float* __restrict__ snew = g_stk[(tb + 1) & 1];
    const float* __restrict__ dvO = g_dv[tb & 1];
    const float4 z4 = make_float4(0.f, 0.f, 0.f, 0.f);
    for (int run = lo_ + ut; run < hi_; run += 256) {
        int ww = run & 31;
        int q = run >> 5;
        int b = q >> 3, dr = q & 7;
        int d0 = dr << 3;
        float pu = cfo[b], po = cfo[256 + b], no = cfo[512 + b];
        const float* cb = &sold[b * NSD * NSW + ww * 4];
        float* ob = &snew[(b * NSD + d0) * NSW + ww * 4];
        float4 v[6];
        v[0] = d0 ? __ldcg((const float4*)(cb + (d0 - 1) * NSW))
                  : __ldcg((const float4*)&dvO[b * NSW + ww * 4]);
#pragma unroll
        for (int i = 0; i < 5; i++)
            v[i + 1] = __ldcg((const float4*)(cb + (d0 + i) * NSW));
#pragma unroll
        for (int i = 0; i < 4; i++) {
            float4 o;
            o.x = no * v[i+1].x + pu * v[i].x + po * v[i+2].x;
            o.y = no * v[i+1].y + pu * v[i].y + po * v[i+2].y;
            o.z = no * v[i+1].z + pu * v[i].z + po * v[i+2].z;
            o.w = no * v[i+1].w + pu * v[i].w + po * v[i+2].w;
            *(float4*)(ob + i * NSW) = o;
        }
        v[0] = v[4]; v[1] = v[5];
#pragma unroll
        for (int i = 0; i < 3; i++)
            v[i + 2] = __ldcg((const float4*)(cb + (d0 + 5 + i) * NSW));
        v[5] = (d0 + 8 < NSD) ? __ldcg((const float4*)(cb + (d0 + 8) * NSW)) : z4;
#pragma unroll
        for (int i = 0; i < 4; i++) {
            float4 o;
            o.x = no * v[i+1].x + pu * v[i].x + po * v[i+2].x;
            o.y = no * v[i+1].y + pu * v[i].y + po * v[i+2].y;
            o.z = no * v[i+1].z + pu * v[i].z + po * v[i+2].z;
            o.w = no * v[i+1].w + pu * v[i].w + po * v[i+2].w;
            *(float4*)(ob + (4 + i) * NSW) = o;
        }
    }
}

// ================= persistent kernel =================
__global__ void __launch_bounds__(NTHR, 1) rnn_persist(
    const float* __restrict__ x, const float* __restrict__ h0,
    float* __restrict__ outs, const float* __restrict__ Wih,
    const float* __restrict__ Whh, const float* __restrict__ Dw,
    const float* __restrict__ Aw,  const float* __restrict__ bih,
    const float* __restrict__ bhh, const float* __restrict__ Db,
    const float* __restrict__ Ab) {
    extern __shared__ char smem[];
    const int tid = threadIdx.x, bx = blockIdx.x;
    const int lane = tid & 31, w = tid >> 5;
    const int gtid = bx * NTHR + tid;

    // ---------- setup ----------
    {
        // gate W fragments: 32 slices x [kc48][q4][lane32][8]
        for (long long i = gtid; i < 32LL * WG_H; i += GSTRIDE) {
            int s = (int)(i / WG_H);
            int j = (int)(i - (long long)s * WG_H);
            int sub = j & 7, lane2 = (j >> 3) & 31, q = (j >> 8) & 3, kc = j >> 10;
            int nt = 2 * q + (sub >> 2);
            int jj = sub & 3;
            int lr = nt * 8 + (lane2 >> 2);
            int grow = (lr >> 4) * NH + s * 16 + (lr & 15);
            int kk = kc * 16 + (lane2 & 3) * 2 + ((jj >> 1) << 3) + (jj & 1);
            g_WGfrag[i] = __float2half(wval(grow, kk, Whh, Wih, Dw, Aw));
        }
        // dv/ctrl W fragments: 5 slices (rows 2048 + s*32 ..)
        for (long long i = gtid; i < 5LL * WD_H; i += GSTRIDE) {
            int s = (int)(i / WD_H);
            int j = (int)(i - (long long)s * WD_H);
            int sub = j & 7, lane2 = (j >> 3) & 31, nh2 = (j >> 8) & 1, kc = j >> 9;
            int nt = nh2 * 2 + (sub >> 2);
            int jj = sub & 3;
            int nrow = 2048 + s * 32 + nt * 8 + (lane2 >> 2);
            int kk = kc * 16 + (lane2 & 3) * 2 + ((jj >> 1) << 3) + (jj & 1);
            g_WDfrag[i] = __float2half(wval(nrow, kk, Whh, Wih, Dw, Aw));
        }
        for (int i = gtid; i < 32 * WS_H; i += GSTRIDE) {
            int s = i >> 13, j = i & (WS_H - 1);
            int sub = j & 7, lane2 = (j >> 3) & 31, ntp = (j >> 8) & 3, kc = j >> 10;
            int nt = ntp * 2 + (sub >> 2);
            int jj = sub & 3;
            int col = nt * 8 + (lane2 >> 2);
            int g = col >> 4, uu = col & 15;
            int jrow = g * NH + s * 16 + uu;
            int kk = kc * 16 + (lane2 & 3) * 2 + ((jj >> 1) << 3) + (jj & 1);
            g_WSfrag[i] = __float2half(Wih[jrow * (NIN + NSW) + NIN + kk]);
        }
        if (gtid < NROWS) {
            float b = 0.f;
            if (gtid < NG)          b = bih[gtid] + bhh[gtid];
            else if (gtid < NG+NSW) b = Db[gtid-NG];
            else if (gtid < NTOT)   b = Ab[gtid-NG-NSW];
            g_bz[gtid] = b;
        }
        for (int i = gtid; i < NB * NH; i += GSTRIDE)
            store_zfrag(i >> 9, i & 511, h0[i]);
        for (int i = gtid; i < NB * NIN; i += GSTRIDE)
            store_zfrag(i >> 8, 512 + (i & 255), x[i]);
    }
    grid_bar(0);

    const bool isGate = (bx < 128);
    const int mT  = isGate ? (bx >> 5) : ((bx - 128) / 5);     // batch half selector
    const int u0  = isGate ? ((bx & 31) << 4) : 0;
    const int s5  = isGate ? 0 : ((bx - 128) % 5);
    const int mb0g = (bx >> 5) << 6;                           // gates CTA batch base

    // blend run-range for this block
    const int TOTR = NB * 8 * 32;
    const int blo = (int)((long long)bx * TOTR / NBLK);
    const int bhi = (int)((long long)(bx + 1) * TOTR / NBLK);
    const int bmid = (blo + bhi) >> 1;

    // load resident W slice
    if (isGate) {
        const uint4* src = (const uint4*)(g_WGfrag + (size_t)(bx & 31) * WG_H);
        uint4* dst = (uint4*)(smem + SMW);
#pragma unroll
        for (int i = 0; i < 12; i++) {
            uint4 v; const uint4* p = src + tid + i * NTHR;
            asm volatile("ld.global.cg.v4.u32 {%0,%1,%2,%3}, [%4];"
                         : "=r"(v.x), "=r"(v.y), "=r"(v.z), "=r"(v.w) : "l"(p));
            dst[tid + i * NTHR] = v;
        }
        const uint4* src2 = (const uint4*)(g_WSfrag + (size_t)(bx & 31) * WS_H);
        uint4* dst2 = (uint4*)(smem + SMWS);
#pragma unroll
        for (int i = 0; i < 2; i++) {
            uint4 v; const uint4* p = src2 + tid + i * NTHR;
            asm volatile("ld.global.cg.v4.u32 {%0,%1,%2,%3}, [%4];"
                         : "=r"(v.x), "=r"(v.y), "=r"(v.z), "=r"(v.w) : "l"(p));
            dst2[tid + i * NTHR] = v;
        }
    } else {
        const uint4* src = (const uint4*)(g_WDfrag + (size_t)s5 * WD_H);
        uint4* dst = (uint4*)(smem + SMW);
#pragma unroll
        for (int i = 0; i < 6; i++) {
            uint4 v; const uint4* p = src + tid + i * NTHR;
            asm volatile("ld.global.cg.v4.u32 {%0,%1,%2,%3}, [%4];"
                         : "=r"(v.x), "=r"(v.y), "=r"(v.z), "=r"(v.w) : "l"(p));
            dst[tid + i * NTHR] = v;
        }
    }
    __syncthreads();

    const char* pB = smem + SMW + lane * 16;
    __half* Sfrag   = (__half*)(smem + SMSF);
    float*  gates_s = (float*)(smem + SMGT);
    float*  cfs     = (float*)(smem + SMCF);
    float*  cfo     = (float*)(smem + SMCFO);

    // per-warp constants
    const int er = lane >> 2, ec2 = (lane & 3) << 1;
    // gates CTA: warp (mt=w&3, nh=w>>2); mtile = mb0g/16 + mt
    const int gmt = w & 3, gnh = w >> 2;           // valid for w<8
    const char* pA_g = (const char*)g_Zfrag + (size_t)((mb0g >> 4) + gmt) * 512 + lane * 16;
    // dv CTA: warp handles mtile mT*8 + (w&7)
    const char* pA_d = (const char*)g_Zfrag + (size_t)(mT * 8 + (w & 7)) * 512 + lane * 16;
    const int n0d = 2048 + s5 * 32;
    const int eb0d = mT * 128 + (w & 7) * 16 + er;

    float bzv[4][2];
    if (isGate) {
#pragma unroll
        for (int q = 0; q < 4; q++) {
            int gc = (gnh * 4 + q) * 8 + ec2;
            int grow = (gc >> 4) * NH + u0 + (gc & 15);
            bzv[q][0] = g_bz[grow]; bzv[q][1] = g_bz[grow + 1];
        }
    } else {
#pragma unroll
        for (int q = 0; q < 4; q++) {
            int col = n0d + q * 8 + ec2;
            bzv[q][0] = g_bz[col]; bzv[q][1] = g_bz[col + 1];
        }
    }

    int ep = 1;
    for (int t = 0; t < SEQT; t++) {
        // ======== phase A window: warps 0-7 MMA(t) || warps 8-15 blend(t-1) part2 ========
        if (w < 8) {
            float acc[4][4];
#pragma unroll
            for (int q = 0; q < 4; q++)
#pragma unroll
                for (int r = 0; r < 4; r++) acc[q][r] = 0.f;

            const char* pA = isGate ? pA_g : pA_d;
            uint4 ab[8];
#pragma unroll
            for (int p = 0; p < 8; p++)
                ab[p] = __ldcg((const uint4*)(pA + p * 8192));

            if (isGate) {
                for (int kc = 0; kc < NKC; kc++) {
                    uint4 A = ab[kc & 7];
                    if (kc < NKC - 8)
                        ab[kc & 7] = __ldcg((const uint4*)(pA + (kc + 8) * 8192));
                    uint4 wv0 = *(const uint4*)(pB + ((kc * 4 + gnh * 2 + 0) << 9));
                    uint4 wv1 = *(const uint4*)(pB + ((kc * 4 + gnh * 2 + 1) << 9));
                    MMA_F16(acc[0], A, wv0.x, wv0.y);
                    MMA_F16(acc[1], A, wv0.z, wv0.w);
                    MMA_F16(acc[2], A, wv1.x, wv1.y);
                    MMA_F16(acc[3], A, wv1.z, wv1.w);
                }
                // epilogue: write G1+bias straight to smem gates_s [bl(64)][gc(64)]
                const int bl0 = gmt * 16 + er;
#pragma unroll
                for (int q = 0; q < 4; q++) {
                    int gc = (gnh * 4 + q) * 8 + ec2;
                    *(float2*)&gates_s[bl0 * 64 + gc] =
                        make_float2(acc[q][0] + bzv[q][0], acc[q][1] + bzv[q][1]);
                    *(float2*)&gates_s[(bl0 + 8) * 64 + gc] =
                        make_float2(acc[q][2] + bzv[q][0], acc[q][3] + bzv[q][1]);
                }
            } else {
                for (int kc = 0; kc < NKC; kc++) {
                    uint4 A = ab[kc & 7];
                    if (kc < NKC - 8)
                        ab[kc & 7] = __ldcg((const uint4*)(pA + (kc + 8) * 8192));
                    uint4 wv0 = *(const uint4*)(pB + ((kc * 2 + 0) << 9));
                    uint4 wv1 = *(const uint4*)(pB + ((kc * 2 + 1) << 9));
                    MMA_F16(acc[0], A, wv0.x, wv0.y);
                    MMA_F16(acc[1], A, wv0.z, wv0.w);
                    MMA_F16(acc[2], A, wv1.x, wv1.y);
                    MMA_F16(acc[3], A, wv1.z, wv1.w);
                }
                if (s5 < 4) {
                    float* dvC = g_dv[t & 1];
#pragma unroll
                    for (int q = 0; q < 4; q++) {
                        int dcol = n0d - NG + q * 8 + ec2;
                        dvC[eb0d * NSW + dcol]           = tanhf(acc[q][0] + bzv[q][0]);
                        dvC[eb0d * NSW + dcol + 1]       = tanhf(acc[q][1] + bzv[q][1]);
                        dvC[(eb0d + 8) * NSW + dcol]     = tanhf(acc[q][2] + bzv[q][0]);
                        dvC[(eb0d + 8) * NSW + dcol + 1] = tanhf(acc[q][3] + bzv[q][1]);
                    }
                } else {
                    if (ec2 < 3) {
                        g_ctrl[eb0d * 3 + ec2]       = acc[0][0] + bzv[0][0];
                        g_ctrl[(eb0d + 8) * 3 + ec2] = acc[0][2] + bzv[0][0];
                    }
                    if (ec2 + 1 < 3) {
                        g_ctrl[eb0d * 3 + ec2 + 1]       = acc[0][1] + bzv[0][1];
                        g_ctrl[(eb0d + 8) * 3 + ec2 + 1] = acc[0][3] + bzv[0][1];
                    }
                    BAR2();
                    if (tid < 128) {
                        int b = mT * 128 + tid;
                        float l0 = g_ctrl[b*3+0], l1 = g_ctrl[b*3+1], l2 = g_ctrl[b*3+2];
                        float mx = fmaxf(l0, fmaxf(l1, l2));
                        float e0 = expf(l0-mx), e1 = expf(l1-mx), e2 = expf(l2-mx);
                        float inv = 1.f / (e0+e1+e2);
                        float* cfC = g_cf[t & 1];
                        cfC[b] = e0*inv; cfC[256+b] = e1*inv; cfC[512+b] = e2*inv;
                    }
                }
            }
        } else if (t > 0) {
            run_blend(t - 1, tid - 256, bmid, bhi, cfo);
        }
        grid_bar(ep); ep++;

        // ======== phase B: gates path (lower) || x-convert + blend(t) part1 (upper) ========
        float* __restrict__ ht = outs + (size_t)t * NB * NH;

        if (tid < 256) {
            if (isGate) {
                const float* __restrict__ sold = g_stk[t & 1];
                const float* __restrict__ dvC = g_dv[t & 1];
                const float* __restrict__ cfC = g_cf[t & 1];
                cfs[tid]       = __ldcg(&cfC[tid]);
                cfs[256 + tid] = __ldcg(&cfC[256 + tid]);
                cfs[512 + tid] = __ldcg(&cfC[512 + tid]);
                BAR1();
                // stack_top -> fp16 A fragments (4 k per thread)
#pragma unroll
                for (int it = 0; it < 8; it++) {
                    int idx = tid + it * 256;
                    int bl = idx >> 5, k4 = (idx & 31) * 4;
                    int b = mb0g + bl;
                    float4 s0 = __ldcg((const float4*)&sold[(b * NSD + 0) * NSW + k4]);
                    float4 s1 = __ldcg((const float4*)&sold[(b * NSD + 1) * NSW + k4]);
                    float4 dd = __ldcg((const float4*)&dvC[b * NSW + k4]);
                    float no = cfs[512+b], pu = cfs[b], po = cfs[256+b];
                    store_sfrag2(Sfrag, bl, k4,
                                 no * s0.x + pu * dd.x + po * s1.x,
                                 no * s0.y + pu * dd.y + po * s1.y);
                    store_sfrag2(Sfrag, bl, k4 + 2,
                                 no * s0.z + pu * dd.z + po * s1.z,
                                 no * s0.w + pu * dd.w + po * s1.w);
                }
                // hoist c state
                float2 hc[2];
#pragma unroll
                for (int j = 0; j < 2; j++) {
                    int p = tid + j * 256;
                    int bl = p >> 3, uu2 = p & 7;
                    hc[j] = *(const float2*)&g_c[(mb0g + bl) * NH + u0 + uu2 * 2];
                }
                BAR1();

                // stack GEMM: acc initialized from gates_s (G1 + bias)
                {
                    const int w8 = tid >> 5;
                    const int mt = w8 & 3, np = (w8 >> 2) * 2, ntb = (w8 >> 2) * 4;
                    const int r0 = mt * 16 + er;
                    float acc[4][4];
#pragma unroll
                    for (int q = 0; q < 4; q++) {
                        int col = (ntb + q) * 8 + ec2;
                        float2 i0 = *(const float2*)&gates_s[r0 * 64 + col];
                        float2 i1 = *(const float2*)&gates_s[(r0 + 8) * 64 + col];
                        acc[q][0] = i0.x; acc[q][1] = i0.y;
                        acc[q][2] = i1.x; acc[q][3] = i1.y;
                    }
#pragma unroll
                    for (int kc = 0; kc < 8; kc++) {
                        uint4 A = *(const uint4*)(smem + SMSF + ((kc * 4 + mt) << 9) + lane * 16);
                        uint4 wv0 = *(const uint4*)(smem + SMWS + (((kc * 4 + np) * 32 + lane) << 4));
                        uint4 wv1 = *(const uint4*)(smem + SMWS + (((kc * 4 + np + 1) * 32 + lane) << 4));
                        MMA_F16(acc[0], A, wv0.x, wv0.y);
                        MMA_F16(acc[1], A, wv0.z, wv0.w);
                        MMA_F16(acc[2], A, wv1.x, wv1.y);
                        MMA_F16(acc[3], A, wv1.z, wv1.w);
                    }
#pragma unroll
                    for (int q = 0; q < 4; q++) {
                        int col = (ntb + q) * 8 + ec2;
                        *(float2*)&gates_s[r0 * 64 + col]       = make_float2(acc[q][0], acc[q][1]);
                        *(float2*)&gates_s[(r0 + 8) * 64 + col] = make_float2(acc[q][2], acc[q][3]);
                    }
                }
                BAR1();

                // LSTM pointwise (paired units) — gates fully in smem
#pragma unroll
                for (int j = 0; j < 2; j++) {
                    int p = tid + j * 256;
                    int bl = p >> 3, uu2 = p & 7;
                    int b = mb0g + bl, u = u0 + uu2 * 2;
                    float2 gsi = *(const float2*)&gates_s[bl * 64 + uu2 * 2];
                    float2 gsf = *(const float2*)&gates_s[bl * 64 + 16 + uu2 * 2];
                    float2 gsg = *(const float2*)&gates_s[bl * 64 + 32 + uu2 * 2];
                    float2 gso = *(const float2*)&gates_s[bl * 64 + 48 + uu2 * 2];
                    float cn0 = sigf(gsf.x) * hc[j].x + sigf(gsi.x) * tanhf(gsg.x);
                    float cn1 = sigf(gsf.y) * hc[j].y + sigf(gsi.y) * tanhf(gsg.y);
                    float hh0 = sigf(gso.x) * tanhf(cn0);
                    float hh1 = sigf(gso.y) * tanhf(cn1);
                    *(float2*)&g_c[b * NH + u] = make_float2(cn0, cn1);
                    *(float2*)&ht[b * NH + u]  = make_float2(hh0, hh1);
                    store_zfrag2(b, u, hh0, hh1);
                }
            }
        } else {
            const int ut = tid - 256;
            if (t + 1 < SEQT) {
                int idx = bx * 256 + ut;
                if (idx < NB * NIN / 2) {
                    const float* __restrict__ xn = x + (size_t)(t + 1) * NB * NIN;
                    int b = idx >> 7, k2 = idx & 127;
                    float2 xv = __ldcg((const float2*)&xn[b * NIN + k2 * 2]);
                    store_zfrag2(b, 512 + k2 * 2, xv.x, xv.y);
                }
            }
            const float* cfC = g_cf[t & 1];
            cfo[ut]       = __ldcg(&cfC[ut]);
            cfo[256 + ut] = __ldcg(&cfC[256 + ut]);
            cfo[512 + ut] = __ldcg(&cfC[512 + ut]);
            BAR3();
            run_blend(t, ut, blo, bmid, cfo);
        }
        grid_bar(ep); ep++;
    }

    // final: blend(SEQT-1) part2
    if (tid >= 256) {
        run_blend(SEQT - 1, tid - 256, bmid, bhi, cfo);
    }
}

// ================= host =================
extern "C" void kernel_launch(void* const* d_in, const int* in_sizes, int n_in,
                              void* d_out, int out_size) {
    const float* x   = (const float*)d_in[0];
    const float* h0  = (const float*)d_in[1];
    const float* c0  = (const float*)d_in[2];
    const float* st0 = (const float*)d_in[3];
    const float* Aw  = (const float*)d_in[4];
    const float* Ab  = (const float*)d_in[5];
    const float* Dw  = (const float*)d_in[6];
    const float* Db  = (const float*)d_in[7];
    const float* Wih = (const float*)d_in[8];
    const float* Whh = (const float*)d_in[9];
    const float* bih = (const float*)d_in[10];
    const float* bhh = (const float*)d_in[11];

    float* outs  = (float*)d_out;
    float* h_out = outs + (size_t)SEQT * NB * NH;
    float* c_out = h_out + (size_t)NB * NH;
    float* s_out = c_out + (size_t)NB * NH;

    float* cbuf;  cudaGetSymbolAddress((void**)&cbuf, g_c);
    float* stbuf; cudaGetSymbolAddress((void**)&stbuf, g_stk);
    unsigned* flagbuf; cudaGetSymbolAddress((void**)&flagbuf, g_flags);

    cudaFuncSetAttribute(rnn_persist, cudaFuncAttributeMaxDynamicSharedMemorySize, SMTOTAL);

    cudaMemcpyAsync(cbuf,  c0,  (size_t)NB * NH * sizeof(float),        cudaMemcpyDeviceToDevice);
    cudaMemcpyAsync(stbuf, st0, (size_t)NB * NSD * NSW * sizeof(float), cudaMemcpyDeviceToDevice);
    cudaMemsetAsync(flagbuf, 0, NBLK * 32 * sizeof(unsigned));

    rnn_persist<<<NBLK, NTHR, SMTOTAL>>>(x, h0, outs, Wih, Whh, Dw, Aw, bih, bhh, Db, Ab);

    const size_t SSZ = (size_t)NB * NSD * NSW;
    cudaMemcpyAsync(h_out, outs + (size_t)(SEQT - 1) * NB * NH,
                    (size_t)NB * NH * sizeof(float), cudaMemcpyDeviceToDevice);
    cudaMemcpyAsync(c_out, cbuf, (size_t)NB * NH * sizeof(float), cudaMemcpyDeviceToDevice);
    cudaMemcpyAsync(s_out, stbuf, SSZ * sizeof(float), cudaMemcpyDeviceToDevice);
}